// round 4
// baseline (speedup 1.0000x reference)
#include <cuda_runtime.h>
#include <cstdint>

#define SEQ   512
#define BATCH 512
#define IDIM  300
#define HDIM  300
#define NP    320          // padded hidden for XP layout
#define JH    152          // per-CTA j-half in scan (2*152 = 304 >= 300)
#define MTOT  (SEQ*BATCH)

#define BM 128
#define BN 160
#define BK 20

#define STHREADS 160
#define HSTRIDE  8
#define HBUF     (304*HSTRIDE)   // one h buffer: [304 j][8 b]
#define WSZ      (IDIM*JH)

// -------- scratch (static device globals; no allocations) --------
__device__ float g_XP[(long long)MTOT * NP];     // ~335 MB
__device__ float g_WihT[IDIM * NP];              // W_ih transposed+padded: [i][j]
__device__ float g_WT[2 * IDIM * JH];            // per-half W_hh transposed: [r][k][jj]
__device__ float g_bias[NP];                     // b_ih + b_hh (padded with 0)

// -------- f32x2 helpers (Blackwell packed fp32, PTX-only) --------
__device__ __forceinline__ unsigned long long pack2(float lo, float hi) {
    unsigned long long r;
    asm("mov.b64 %0, {%1, %2};" : "=l"(r) : "f"(lo), "f"(hi));
    return r;
}
__device__ __forceinline__ unsigned long long bcast2(float v) {
    unsigned long long r;
    asm("mov.b64 %0, {%1, %1};" : "=l"(r) : "f"(v));
    return r;
}
__device__ __forceinline__ void ffma2(unsigned long long& d, unsigned long long a, unsigned long long b) {
    asm("fma.rn.f32x2 %0, %1, %2, %3;" : "=l"(d) : "l"(a), "l"(b), "l"(d));
}
__device__ __forceinline__ void unpack2(unsigned long long v, float& lo, float& hi) {
    asm("mov.b64 {%0, %1}, %2;" : "=f"(lo), "=f"(hi) : "l"(v));
}
__device__ __forceinline__ uint32_t smem_u32(const void* p) {
    uint32_t a;
    asm("{ .reg .u64 t; cvta.to.shared.u64 t, %1; cvt.u32.u64 %0, t; }" : "=r"(a) : "l"(p));
    return a;
}

// -------- prep: transposes / padding / bias fold --------
__global__ void prep_kernel(const float* __restrict__ Wih, const float* __restrict__ Whh,
                            const float* __restrict__ bih, const float* __restrict__ bhh) {
    int i = blockIdx.x * blockDim.x + threadIdx.x;
    if (i < IDIM * NP) {
        int r = i / NP, j = i % NP;
        g_WihT[i] = (j < HDIM) ? Wih[j * IDIM + r] : 0.f;
    }
    if (i < 2 * IDIM * JH) {
        int rr  = i / (IDIM * JH);
        int rem = i % (IDIM * JH);
        int k = rem / JH, jj = rem % JH;
        int j = rr * JH + jj;
        g_WT[i] = (j < HDIM) ? Whh[j * HDIM + k] : 0.f;
    }
    if (i < NP) g_bias[i] = (i < HDIM) ? (bih[i] + bhh[i]) : 0.f;
}

// -------- x_proj GEMM: XP[m][j] = IN[m][:] . W_ih[j][:] + bias[j] --------
__global__ __launch_bounds__(256) void gemm_xproj(const float* __restrict__ IN) {
    __shared__ float As[BM][BK + 1];  // [m][k], padded
    __shared__ float Bs[BK][BN];      // [k][n], n contiguous
    int tid = threadIdx.x;
    int m0 = blockIdx.y * BM;
    int n0 = blockIdx.x * BN;
    int mth = tid >> 4, nth = tid & 15;
    int tm0 = mth * 8, tn0 = nth * 10;

    unsigned long long acc[8][5];
    #pragma unroll
    for (int i = 0; i < 8; i++)
        #pragma unroll
        for (int u = 0; u < 5; u++) acc[i][u] = 0ull;

    float bias[10];
    #pragma unroll
    for (int u = 0; u < 10; u++) bias[u] = g_bias[n0 + tn0 + u];

    for (int kk = 0; kk < IDIM; kk += BK) {
        #pragma unroll
        for (int l = 0; l < (BM * BK) / 256; l++) {
            int idx = tid + l * 256;
            int k = idx % BK, m = idx / BK;
            As[m][k] = IN[(long long)(m0 + m) * IDIM + kk + k];
        }
        for (int idx = tid * 4; idx < BK * BN; idx += 256 * 4) {
            int k = idx / BN, n = idx % BN;
            *(float4*)&Bs[k][n] = *(const float4*)&g_WihT[(long long)(kk + k) * NP + n0 + n];
        }
        __syncthreads();
        #pragma unroll 4
        for (int k = 0; k < BK; k++) {
            float a[8];
            #pragma unroll
            for (int i = 0; i < 8; i++) a[i] = As[tm0 + i][k];
            unsigned long long bv[5];
            const unsigned long long* Bk = (const unsigned long long*)&Bs[k][tn0];
            #pragma unroll
            for (int u = 0; u < 5; u++) bv[u] = Bk[u];
            #pragma unroll
            for (int i = 0; i < 8; i++) {
                unsigned long long aa = bcast2(a[i]);
                #pragma unroll
                for (int u = 0; u < 5; u++) ffma2(acc[i][u], aa, bv[u]);
            }
        }
        __syncthreads();
    }
    #pragma unroll
    for (int i = 0; i < 8; i++) {
        long long row = (long long)(m0 + tm0 + i) * NP + n0 + tn0;
        #pragma unroll
        for (int u = 0; u < 5; u++) {
            float lo, hi; unpack2(acc[i][u], lo, hi);
            float2 v = make_float2(lo + bias[2 * u], hi + bias[2 * u + 1]);
            *(float2*)&g_XP[row + 2 * u] = v;
        }
    }
}

// -------- recurrent scan: 64 clusters x 2 CTAs, 8 batch per cluster --------
// CTA rank r holds W_hh rows j in [152r, 152r+152) transposed in smem (k-major).
// Per step: each CTA computes its h-half, writes it to BOTH CTAs' h buffers
// (local STS + st.shared::cluster to peer), then barrier.cluster.
__global__ __cluster_dims__(2, 1, 1) __launch_bounds__(STHREADS, 1)
void scan_kernel(float* __restrict__ out) {
    extern __shared__ float sm[];
    float* WT = sm;            // [300][152]
    float* H  = sm + WSZ;      // [2][304][8] double-buffered h, layout [k][b]
    int tid = threadIdx.x;
    unsigned rank;
    asm("mov.u32 %0, %%cluster_ctarank;" : "=r"(rank));
    int cid = blockIdx.x >> 1;

    const float* WTg = g_WT + rank * WSZ;
    for (int i = tid; i < WSZ; i += STHREADS) WT[i] = WTg[i];
    for (int i = tid; i < 2 * HBUF; i += STHREADS) H[i] = 0.f;
    asm volatile("barrier.cluster.arrive.aligned;" ::: "memory");
    asm volatile("barrier.cluster.wait.aligned;" ::: "memory");

    int jg = tid % 76, bg = tid / 76;   // 2 j's per thread, 4 b's per thread
    bool active = tid < 152;
    int j0 = jg * 2;
    int jglob = rank * JH + j0;         // global j of acc lane 0
    int bloc = bg * 4;                  // 0 or 4
    int bglob = cid * 8 + bloc;
    uint32_t hbase32 = smem_u32(H);
    unsigned peer = rank ^ 1u;
    int p = 0;

    for (int t = 0; t < SEQ; t++) {
        unsigned long long a0 = 0, a1 = 0, a2 = 0, a3 = 0;
        if (active) {
            const float* xr = g_XP + (long long)(t * BATCH + bglob) * NP + jglob;
            float2 x0 = *(const float2*)(xr);
            float2 x1 = *(const float2*)(xr + NP);
            float2 x2 = *(const float2*)(xr + 2 * NP);
            float2 x3 = *(const float2*)(xr + 3 * NP);
            a0 = pack2(x0.x, x0.y);
            a1 = pack2(x1.x, x1.y);
            a2 = pack2(x2.x, x2.y);
            a3 = pack2(x3.x, x3.y);
            const float* Hp = H + p * HBUF;
            #pragma unroll 5
            for (int k = 0; k < IDIM; k++) {
                unsigned long long w = *(const unsigned long long*)(WT + k * JH + j0);
                float4 h4 = *(const float4*)(Hp + k * HSTRIDE + bloc);
                ffma2(a0, w, bcast2(h4.x));
                ffma2(a1, w, bcast2(h4.y));
                ffma2(a2, w, bcast2(h4.z));
                ffma2(a3, w, bcast2(h4.w));
            }
            float v0l, v0h, v1l, v1h, v2l, v2h, v3l, v3h;
            unpack2(a0, v0l, v0h); unpack2(a1, v1l, v1h);
            unpack2(a2, v2l, v2h); unpack2(a3, v3l, v3h);
            float4 lo4 = make_float4(tanhf(v0l), tanhf(v1l), tanhf(v2l), tanhf(v3l));
            float4 hi4 = make_float4(tanhf(v0h), tanhf(v1h), tanhf(v2h), tanhf(v3h));
            int off0 = (1 - p) * HBUF + jglob * HSTRIDE + bloc;   // row j0
            int off1 = off0 + HSTRIDE;                            // row j0+1
            *(float4*)(H + off0) = lo4;
            *(float4*)(H + off1) = hi4;
            uint32_t r0 = hbase32 + off0 * 4;
            uint32_t r1 = hbase32 + off1 * 4;
            asm volatile("{ .reg .b32 ra; .reg .b64 d; mov.b64 d, {%2,%3}; "
                         "mapa.shared::cluster.u32 ra, %0, %1; st.shared::cluster.b64 [ra], d; }"
                         :: "r"(r0), "r"(peer), "f"(lo4.x), "f"(lo4.y) : "memory");
            asm volatile("{ .reg .b32 ra; .reg .b64 d; mov.b64 d, {%2,%3}; "
                         "mapa.shared::cluster.u32 ra, %0, %1; st.shared::cluster.b64 [ra], d; }"
                         :: "r"(r0 + 8u), "r"(peer), "f"(lo4.z), "f"(lo4.w) : "memory");
            asm volatile("{ .reg .b32 ra; .reg .b64 d; mov.b64 d, {%2,%3}; "
                         "mapa.shared::cluster.u32 ra, %0, %1; st.shared::cluster.b64 [ra], d; }"
                         :: "r"(r1), "r"(peer), "f"(hi4.x), "f"(hi4.y) : "memory");
            asm volatile("{ .reg .b32 ra; .reg .b64 d; mov.b64 d, {%2,%3}; "
                         "mapa.shared::cluster.u32 ra, %0, %1; st.shared::cluster.b64 [ra], d; }"
                         :: "r"(r1 + 8u), "r"(peer), "f"(hi4.z), "f"(hi4.w) : "memory");
        }
        asm volatile("barrier.cluster.arrive.aligned;" ::: "memory");
        asm volatile("barrier.cluster.wait.aligned;" ::: "memory");
        p ^= 1;
    }

    // write final h: each CTA writes its j-half for the cluster's 8 batches
    const float* Hf = H + p * HBUF;
    int cb0 = cid * 8;
    for (int idx = tid; idx < 8 * JH; idx += STHREADS) {
        int b = idx / JH, jj = idx % JH;
        int j = rank * JH + jj;
        if (j < HDIM) out[(long long)(cb0 + b) * HDIM + j] = Hf[j * HSTRIDE + b];
    }
}

extern "C" void kernel_launch(void* const* d_in, const int* in_sizes, int n_in,
                              void* d_out, int out_size) {
    const float* IN  = (const float*)d_in[0];
    const float* Wih = (const float*)d_in[1];
    const float* Whh = (const float*)d_in[2];
    const float* bih = (const float*)d_in[3];
    const float* bhh = (const float*)d_in[4];
    float* out = (float*)d_out;

    prep_kernel<<<(IDIM * NP + 255) / 256, 256>>>(Wih, Whh, bih, bhh);

    dim3 g(NP / BN, MTOT / BM);   // (2, 2048)
    gemm_xproj<<<g, 256>>>(IN);

    size_t smem = (size_t)(WSZ + 2 * HBUF) * sizeof(float);  // 201,856 B
    cudaFuncSetAttribute(scan_kernel, cudaFuncAttributeMaxDynamicSharedMemorySize, (int)smem);
    scan_kernel<<<128, STHREADS, smem>>>(out);
}

// round 5
// speedup vs baseline: 1.0021x; 1.0021x over previous
#include <cuda_runtime.h>
#include <cstdint>

#define SEQ   512
#define BATCH 512
#define IDIM  300
#define HDIM  300
#define NP    320          // padded hidden for XP layout
#define JH    152          // per-CTA j-half in scan (2*152 = 304 >= 300)
#define MTOT  (SEQ*BATCH)

#define BM 128
#define BN 160
#define BK 20

#define STHREADS 160
#define HSTRIDE  8
#define HBUF     (304*HSTRIDE)   // one h buffer: [304 j][8 b]
#define WSZ      (IDIM*JH)

// -------- scratch (static device globals; no allocations) --------
__device__ float g_XP[(long long)MTOT * NP];     // ~335 MB
__device__ float g_WihT[IDIM * NP];              // W_ih transposed+padded: [i][j]
__device__ float g_WT[2 * IDIM * JH];            // per-half W_hh transposed: [r][k][jj]
__device__ float g_bias[NP];                     // b_ih + b_hh (padded with 0)

// -------- f32x2 helpers (Blackwell packed fp32, PTX-only) --------
__device__ __forceinline__ unsigned long long pack2(float lo, float hi) {
    unsigned long long r;
    asm("mov.b64 %0, {%1, %2};" : "=l"(r) : "f"(lo), "f"(hi));
    return r;
}
__device__ __forceinline__ unsigned long long bcast2(float v) {
    unsigned long long r;
    asm("mov.b64 %0, {%1, %1};" : "=l"(r) : "f"(v));
    return r;
}
__device__ __forceinline__ void ffma2(unsigned long long& d, unsigned long long a, unsigned long long b) {
    asm("fma.rn.f32x2 %0, %1, %2, %3;" : "=l"(d) : "l"(a), "l"(b), "l"(d));
}
__device__ __forceinline__ void unpack2(unsigned long long v, float& lo, float& hi) {
    asm("mov.b64 {%0, %1}, %2;" : "=f"(lo), "=f"(hi) : "l"(v));
}
__device__ __forceinline__ uint32_t smem_u32(const void* p) {
    uint32_t a;
    asm("{ .reg .u64 t; cvta.to.shared.u64 t, %1; cvt.u32.u64 %0, t; }" : "=r"(a) : "l"(p));
    return a;
}

// -------- prep: transposes / padding / bias fold --------
__global__ void prep_kernel(const float* __restrict__ Wih, const float* __restrict__ Whh,
                            const float* __restrict__ bih, const float* __restrict__ bhh) {
    int i = blockIdx.x * blockDim.x + threadIdx.x;
    if (i < IDIM * NP) {
        int r = i / NP, j = i % NP;
        g_WihT[i] = (j < HDIM) ? Wih[j * IDIM + r] : 0.f;
    }
    if (i < 2 * IDIM * JH) {
        int rr  = i / (IDIM * JH);
        int rem = i % (IDIM * JH);
        int k = rem / JH, jj = rem % JH;
        int j = rr * JH + jj;
        g_WT[i] = (j < HDIM) ? Whh[j * HDIM + k] : 0.f;
    }
    if (i < NP) g_bias[i] = (i < HDIM) ? (bih[i] + bhh[i]) : 0.f;
}

// -------- x_proj GEMM: XP[m][j] = IN[m][:] . W_ih[j][:] + bias[j] --------
__global__ __launch_bounds__(256) void gemm_xproj(const float* __restrict__ IN) {
    __shared__ float As[BM][BK + 1];  // [m][k], padded
    __shared__ float Bs[BK][BN];      // [k][n], n contiguous
    int tid = threadIdx.x;
    int m0 = blockIdx.y * BM;
    int n0 = blockIdx.x * BN;
    int mth = tid >> 4, nth = tid & 15;
    int tm0 = mth * 8, tn0 = nth * 10;

    unsigned long long acc[8][5];
    #pragma unroll
    for (int i = 0; i < 8; i++)
        #pragma unroll
        for (int u = 0; u < 5; u++) acc[i][u] = 0ull;

    float bias[10];
    #pragma unroll
    for (int u = 0; u < 10; u++) bias[u] = g_bias[n0 + tn0 + u];

    for (int kk = 0; kk < IDIM; kk += BK) {
        #pragma unroll
        for (int l = 0; l < (BM * BK) / 256; l++) {
            int idx = tid + l * 256;
            int k = idx % BK, m = idx / BK;
            As[m][k] = IN[(long long)(m0 + m) * IDIM + kk + k];
        }
        for (int idx = tid * 4; idx < BK * BN; idx += 256 * 4) {
            int k = idx / BN, n = idx % BN;
            *(float4*)&Bs[k][n] = *(const float4*)&g_WihT[(long long)(kk + k) * NP + n0 + n];
        }
        __syncthreads();
        #pragma unroll 4
        for (int k = 0; k < BK; k++) {
            float a[8];
            #pragma unroll
            for (int i = 0; i < 8; i++) a[i] = As[tm0 + i][k];
            unsigned long long bv[5];
            const unsigned long long* Bk = (const unsigned long long*)&Bs[k][tn0];
            #pragma unroll
            for (int u = 0; u < 5; u++) bv[u] = Bk[u];
            #pragma unroll
            for (int i = 0; i < 8; i++) {
                unsigned long long aa = bcast2(a[i]);
                #pragma unroll
                for (int u = 0; u < 5; u++) ffma2(acc[i][u], aa, bv[u]);
            }
        }
        __syncthreads();
    }
    #pragma unroll
    for (int i = 0; i < 8; i++) {
        long long row = (long long)(m0 + tm0 + i) * NP + n0 + tn0;
        #pragma unroll
        for (int u = 0; u < 5; u++) {
            float lo, hi; unpack2(acc[i][u], lo, hi);
            float2 v = make_float2(lo + bias[2 * u], hi + bias[2 * u + 1]);
            *(float2*)&g_XP[row + 2 * u] = v;
        }
    }
}

// -------- recurrent scan: 64 clusters x 2 CTAs, 8 batch per cluster --------
// CTA rank r holds W_hh rows j in [152r, 152r+152) transposed in smem (k-major).
// Per step: each CTA computes its h-half, writes it to BOTH CTAs' h buffers
// (local STS + st.shared::cluster to peer), then barrier.cluster.
__global__ __cluster_dims__(2, 1, 1) __launch_bounds__(STHREADS, 1)
void scan_kernel(float* __restrict__ out) {
    extern __shared__ float sm[];
    float* WT = sm;            // [300][152]
    float* H  = sm + WSZ;      // [2][304][8] double-buffered h, layout [k][b]
    int tid = threadIdx.x;
    unsigned rank;
    asm("mov.u32 %0, %%cluster_ctarank;" : "=r"(rank));
    int cid = blockIdx.x >> 1;

    const float* WTg = g_WT + rank * WSZ;
    for (int i = tid; i < WSZ; i += STHREADS) WT[i] = WTg[i];
    for (int i = tid; i < 2 * HBUF; i += STHREADS) H[i] = 0.f;
    asm volatile("barrier.cluster.arrive.aligned;" ::: "memory");
    asm volatile("barrier.cluster.wait.aligned;" ::: "memory");

    int jg = tid % 76, bg = tid / 76;   // 2 j's per thread, 4 b's per thread
    bool active = tid < 152;
    int j0 = jg * 2;
    int jglob = rank * JH + j0;         // global j of acc lane 0
    int bloc = bg * 4;                  // 0 or 4
    int bglob = cid * 8 + bloc;
    uint32_t hbase32 = smem_u32(H);
    unsigned peer = rank ^ 1u;
    int p = 0;

    for (int t = 0; t < SEQ; t++) {
        unsigned long long a0 = 0, a1 = 0, a2 = 0, a3 = 0;
        if (active) {
            const float* xr = g_XP + (long long)(t * BATCH + bglob) * NP + jglob;
            float2 x0 = *(const float2*)(xr);
            float2 x1 = *(const float2*)(xr + NP);
            float2 x2 = *(const float2*)(xr + 2 * NP);
            float2 x3 = *(const float2*)(xr + 3 * NP);
            a0 = pack2(x0.x, x0.y);
            a1 = pack2(x1.x, x1.y);
            a2 = pack2(x2.x, x2.y);
            a3 = pack2(x3.x, x3.y);
            const float* Hp = H + p * HBUF;
            #pragma unroll 5
            for (int k = 0; k < IDIM; k++) {
                unsigned long long w = *(const unsigned long long*)(WT + k * JH + j0);
                float4 h4 = *(const float4*)(Hp + k * HSTRIDE + bloc);
                ffma2(a0, w, bcast2(h4.x));
                ffma2(a1, w, bcast2(h4.y));
                ffma2(a2, w, bcast2(h4.z));
                ffma2(a3, w, bcast2(h4.w));
            }
            float v0l, v0h, v1l, v1h, v2l, v2h, v3l, v3h;
            unpack2(a0, v0l, v0h); unpack2(a1, v1l, v1h);
            unpack2(a2, v2l, v2h); unpack2(a3, v3l, v3h);
            float4 lo4 = make_float4(tanhf(v0l), tanhf(v1l), tanhf(v2l), tanhf(v3l));
            float4 hi4 = make_float4(tanhf(v0h), tanhf(v1h), tanhf(v2h), tanhf(v3h));
            int off0 = (1 - p) * HBUF + jglob * HSTRIDE + bloc;   // row j0
            int off1 = off0 + HSTRIDE;                            // row j0+1
            *(float4*)(H + off0) = lo4;
            *(float4*)(H + off1) = hi4;
            uint32_t r0 = hbase32 + off0 * 4;
            uint32_t r1 = hbase32 + off1 * 4;
            asm volatile("{ .reg .b32 ra; .reg .b64 d; mov.b64 d, {%2,%3}; "
                         "mapa.shared::cluster.u32 ra, %0, %1; st.shared::cluster.b64 [ra], d; }"
                         :: "r"(r0), "r"(peer), "f"(lo4.x), "f"(lo4.y) : "memory");
            asm volatile("{ .reg .b32 ra; .reg .b64 d; mov.b64 d, {%2,%3}; "
                         "mapa.shared::cluster.u32 ra, %0, %1; st.shared::cluster.b64 [ra], d; }"
                         :: "r"(r0 + 8u), "r"(peer), "f"(lo4.z), "f"(lo4.w) : "memory");
            asm volatile("{ .reg .b32 ra; .reg .b64 d; mov.b64 d, {%2,%3}; "
                         "mapa.shared::cluster.u32 ra, %0, %1; st.shared::cluster.b64 [ra], d; }"
                         :: "r"(r1), "r"(peer), "f"(hi4.x), "f"(hi4.y) : "memory");
            asm volatile("{ .reg .b32 ra; .reg .b64 d; mov.b64 d, {%2,%3}; "
                         "mapa.shared::cluster.u32 ra, %0, %1; st.shared::cluster.b64 [ra], d; }"
                         :: "r"(r1 + 8u), "r"(peer), "f"(hi4.z), "f"(hi4.w) : "memory");
        }
        asm volatile("barrier.cluster.arrive.aligned;" ::: "memory");
        asm volatile("barrier.cluster.wait.aligned;" ::: "memory");
        p ^= 1;
    }

    // write final h: each CTA writes its j-half for the cluster's 8 batches
    const float* Hf = H + p * HBUF;
    int cb0 = cid * 8;
    for (int idx = tid; idx < 8 * JH; idx += STHREADS) {
        int b = idx / JH, jj = idx % JH;
        int j = rank * JH + jj;
        if (j < HDIM) out[(long long)(cb0 + b) * HDIM + j] = Hf[j * HSTRIDE + b];
    }
}

extern "C" void kernel_launch(void* const* d_in, const int* in_sizes, int n_in,
                              void* d_out, int out_size) {
    const float* IN  = (const float*)d_in[0];
    const float* Wih = (const float*)d_in[1];
    const float* Whh = (const float*)d_in[2];
    const float* bih = (const float*)d_in[3];
    const float* bhh = (const float*)d_in[4];
    float* out = (float*)d_out;

    prep_kernel<<<(IDIM * NP + 255) / 256, 256>>>(Wih, Whh, bih, bhh);

    dim3 g(NP / BN, MTOT / BM);   // (2, 2048)
    gemm_xproj<<<g, 256>>>(IN);

    size_t smem = (size_t)(WSZ + 2 * HBUF) * sizeof(float);  // 201,856 B
    cudaFuncSetAttribute(scan_kernel, cudaFuncAttributeMaxDynamicSharedMemorySize, (int)smem);
    scan_kernel<<<128, STHREADS, smem>>>(out);
}

// round 6
// speedup vs baseline: 1.0725x; 1.0702x over previous
#include <cuda_runtime.h>
#include <cstdint>

#define SEQ   512
#define BATCH 512
#define IDIM  300
#define HDIM  300
#define NP    320          // padded hidden for XP layout
#define JH    152          // per-CTA j-half in scan (2*152 = 304 >= 300)
#define MTOT  (SEQ*BATCH)

#define BM 128
#define BN 160
#define BK 20

// scan config: 608 threads = 76 j-pairs x 2 b-groups x 4 k-quarters
#define STHREADS 608
#define KQ       4
#define KCH      (IDIM/KQ)       // 75
#define HSTRIDE  8
#define HBUF     (304*HSTRIDE)   // one h buffer: [304 j][8 b]
#define WSZ      (IDIM*JH)
#define NBASE    152             // base threads (kq==0)
#define PARTSZ   ((KQ-1)*NBASE*8)  // 3648 floats

// -------- scratch (static device globals; no allocations) --------
__device__ float g_XP[(long long)MTOT * NP];     // ~335 MB
__device__ float g_WihT[IDIM * NP];              // W_ih transposed+padded: [i][j]
__device__ float g_WT[2 * IDIM * JH];            // per-half W_hh transposed: [r][k][jj]
__device__ float g_bias[NP];                     // b_ih + b_hh (padded with 0)

// -------- f32x2 helpers (Blackwell packed fp32, PTX-only) --------
__device__ __forceinline__ unsigned long long pack2(float lo, float hi) {
    unsigned long long r;
    asm("mov.b64 %0, {%1, %2};" : "=l"(r) : "f"(lo), "f"(hi));
    return r;
}
__device__ __forceinline__ unsigned long long bcast2(float v) {
    unsigned long long r;
    asm("mov.b64 %0, {%1, %1};" : "=l"(r) : "f"(v));
    return r;
}
__device__ __forceinline__ void ffma2(unsigned long long& d, unsigned long long a, unsigned long long b) {
    asm("fma.rn.f32x2 %0, %1, %2, %3;" : "=l"(d) : "l"(a), "l"(b), "l"(d));
}
__device__ __forceinline__ void fadd2(unsigned long long& d, unsigned long long a) {
    asm("add.rn.f32x2 %0, %1, %2;" : "=l"(d) : "l"(d), "l"(a));
}
__device__ __forceinline__ void unpack2(unsigned long long v, float& lo, float& hi) {
    asm("mov.b64 {%0, %1}, %2;" : "=f"(lo), "=f"(hi) : "l"(v));
}
__device__ __forceinline__ uint32_t smem_u32(const void* p) {
    uint32_t a;
    asm("{ .reg .u64 t; cvta.to.shared.u64 t, %1; cvt.u32.u64 %0, t; }" : "=r"(a) : "l"(p));
    return a;
}

// -------- prep: transposes / padding / bias fold --------
__global__ void prep_kernel(const float* __restrict__ Wih, const float* __restrict__ Whh,
                            const float* __restrict__ bih, const float* __restrict__ bhh) {
    int i = blockIdx.x * blockDim.x + threadIdx.x;
    if (i < IDIM * NP) {
        int r = i / NP, j = i % NP;
        g_WihT[i] = (j < HDIM) ? Wih[j * IDIM + r] : 0.f;
    }
    if (i < 2 * IDIM * JH) {
        int rr  = i / (IDIM * JH);
        int rem = i % (IDIM * JH);
        int k = rem / JH, jj = rem % JH;
        int j = rr * JH + jj;
        g_WT[i] = (j < HDIM) ? Whh[j * HDIM + k] : 0.f;
    }
    if (i < NP) g_bias[i] = (i < HDIM) ? (bih[i] + bhh[i]) : 0.f;
}

// -------- x_proj GEMM: XP[m][j] = IN[m][:] . W_ih[j][:] + bias[j] --------
__global__ __launch_bounds__(256) void gemm_xproj(const float* __restrict__ IN) {
    __shared__ float As[BM][BK + 1];  // [m][k], padded
    __shared__ float Bs[BK][BN];      // [k][n], n contiguous
    int tid = threadIdx.x;
    int m0 = blockIdx.y * BM;
    int n0 = blockIdx.x * BN;
    int mth = tid >> 4, nth = tid & 15;
    int tm0 = mth * 8, tn0 = nth * 10;

    unsigned long long acc[8][5];
    #pragma unroll
    for (int i = 0; i < 8; i++)
        #pragma unroll
        for (int u = 0; u < 5; u++) acc[i][u] = 0ull;

    float bias[10];
    #pragma unroll
    for (int u = 0; u < 10; u++) bias[u] = g_bias[n0 + tn0 + u];

    for (int kk = 0; kk < IDIM; kk += BK) {
        #pragma unroll
        for (int l = 0; l < (BM * BK) / 256; l++) {
            int idx = tid + l * 256;
            int k = idx % BK, m = idx / BK;
            As[m][k] = IN[(long long)(m0 + m) * IDIM + kk + k];
        }
        for (int idx = tid * 4; idx < BK * BN; idx += 256 * 4) {
            int k = idx / BN, n = idx % BN;
            *(float4*)&Bs[k][n] = *(const float4*)&g_WihT[(long long)(kk + k) * NP + n0 + n];
        }
        __syncthreads();
        #pragma unroll 4
        for (int k = 0; k < BK; k++) {
            float a[8];
            #pragma unroll
            for (int i = 0; i < 8; i++) a[i] = As[tm0 + i][k];
            unsigned long long bv[5];
            const unsigned long long* Bk = (const unsigned long long*)&Bs[k][tn0];
            #pragma unroll
            for (int u = 0; u < 5; u++) bv[u] = Bk[u];
            #pragma unroll
            for (int i = 0; i < 8; i++) {
                unsigned long long aa = bcast2(a[i]);
                #pragma unroll
                for (int u = 0; u < 5; u++) ffma2(acc[i][u], aa, bv[u]);
            }
        }
        __syncthreads();
    }
    #pragma unroll
    for (int i = 0; i < 8; i++) {
        long long row = (long long)(m0 + tm0 + i) * NP + n0 + tn0;
        #pragma unroll
        for (int u = 0; u < 5; u++) {
            float lo, hi; unpack2(acc[i][u], lo, hi);
            float2 v = make_float2(lo + bias[2 * u], hi + bias[2 * u + 1]);
            *(float2*)&g_XP[row + 2 * u] = v;
        }
    }
}

// -------- recurrent scan: 64 clusters x 2 CTAs, 8 batch per cluster --------
// 608 threads/CTA: thread = (j-pair, b-group of 4, k-quarter of 75).
// Inner loop per k: LDS.64 (w pair) + LDS.128 (4 h, pre-packed f32x2 over b)
// + 2 bcast + 4 FFMA2  ->  8 instr / 16 MAC  (FFMA2-throughput bound).
// k-quarter partials reduced via smem; base threads (kq==0) finish:
// + xp, tanh, write h to local + peer CTA smem, then cluster barrier.
__global__ __cluster_dims__(2, 1, 1) __launch_bounds__(STHREADS, 1)
void scan_kernel(float* __restrict__ out) {
    extern __shared__ float sm[];
    float* WT   = sm;                   // [300][152]
    float* H    = sm + WSZ;             // [2][304][8] double-buffered h, layout [k][b]
    float* PART = H + 2 * HBUF;         // [3][152][8] k-quarter partials
    int tid = threadIdx.x;
    unsigned rank;
    asm("mov.u32 %0, %%cluster_ctarank;" : "=r"(rank));
    int cid = blockIdx.x >> 1;

    const float* WTg = g_WT + rank * WSZ;
    for (int i = tid; i < WSZ; i += STHREADS) WT[i] = WTg[i];
    for (int i = tid; i < 2 * HBUF; i += STHREADS) H[i] = 0.f;
    asm volatile("barrier.cluster.arrive.aligned;" ::: "memory");
    asm volatile("barrier.cluster.wait.aligned;" ::: "memory");

    int jp = tid % 76;                  // j-pair index
    int bg = (tid / 76) & 1;            // b-group (0: b0-3, 1: b4-7)
    int kq = tid / 152;                 // k-quarter 0..3
    int j0 = jp * 2;
    int jglob = rank * JH + j0;
    int bloc = bg * 4;
    int bglob = cid * 8 + bloc;
    int kstart = kq * KCH;
    bool base = (kq == 0);
    int slot = bg * 76 + jp;            // 0..151
    uint32_t hbase32 = smem_u32(H);
    unsigned peer = rank ^ 1u;
    int p = 0;

    for (int t = 0; t < SEQ; t++) {
        unsigned long long a00, a01, a10, a11;   // packed over b: (b0,b1),(b2,b3) x rows j0,j0+1
        if (base) {
            const float* xr = g_XP + (long long)(t * BATCH + bglob) * NP + jglob;
            float2 x0 = *(const float2*)(xr);
            float2 x1 = *(const float2*)(xr + NP);
            float2 x2 = *(const float2*)(xr + 2 * NP);
            float2 x3 = *(const float2*)(xr + 3 * NP);
            a00 = pack2(x0.x, x1.x);    // row j0,   b0,b1
            a01 = pack2(x2.x, x3.x);    // row j0,   b2,b3
            a10 = pack2(x0.y, x1.y);    // row j0+1, b0,b1
            a11 = pack2(x2.y, x3.y);    // row j0+1, b2,b3
        } else {
            a00 = a01 = a10 = a11 = 0ull;
        }
        const float* Wp = WT + kstart * JH + j0;
        const float* hp = H + p * HBUF + kstart * HSTRIDE + bloc;
        #pragma unroll 5
        for (int kk = 0; kk < KCH; kk++) {
            float2 w = *(const float2*)(Wp + kk * JH);
            const unsigned long long* hv = (const unsigned long long*)(hp + kk * HSTRIDE);
            unsigned long long h01 = hv[0];
            unsigned long long h23 = hv[1];
            unsigned long long w0 = bcast2(w.x);
            unsigned long long w1 = bcast2(w.y);
            ffma2(a00, w0, h01);
            ffma2(a01, w0, h23);
            ffma2(a10, w1, h01);
            ffma2(a11, w1, h23);
        }
        if (!base) {
            unsigned long long* dst = (unsigned long long*)(PART + ((kq - 1) * NBASE + slot) * 8);
            dst[0] = a00; dst[1] = a01; dst[2] = a10; dst[3] = a11;
        }
        __syncthreads();
        if (base) {
            #pragma unroll
            for (int q = 1; q < KQ; q++) {
                const unsigned long long* src =
                    (const unsigned long long*)(PART + ((q - 1) * NBASE + slot) * 8);
                fadd2(a00, src[0]); fadd2(a01, src[1]);
                fadd2(a10, src[2]); fadd2(a11, src[3]);
            }
            float v0l, v0h, v1l, v1h, v2l, v2h, v3l, v3h;
            unpack2(a00, v0l, v0h); unpack2(a01, v1l, v1h);
            unpack2(a10, v2l, v2h); unpack2(a11, v3l, v3h);
            float4 lo4 = make_float4(tanhf(v0l), tanhf(v0h), tanhf(v1l), tanhf(v1h));  // row j0, b0..b3
            float4 hi4 = make_float4(tanhf(v2l), tanhf(v2h), tanhf(v3l), tanhf(v3h));  // row j0+1
            int off0 = (1 - p) * HBUF + jglob * HSTRIDE + bloc;
            int off1 = off0 + HSTRIDE;
            *(float4*)(H + off0) = lo4;
            *(float4*)(H + off1) = hi4;
            uint32_t r0 = hbase32 + off0 * 4;
            uint32_t r1 = hbase32 + off1 * 4;
            asm volatile("{ .reg .b32 ra; .reg .b64 d; mov.b64 d, {%2,%3}; "
                         "mapa.shared::cluster.u32 ra, %0, %1; st.shared::cluster.b64 [ra], d; }"
                         :: "r"(r0), "r"(peer), "f"(lo4.x), "f"(lo4.y) : "memory");
            asm volatile("{ .reg .b32 ra; .reg .b64 d; mov.b64 d, {%2,%3}; "
                         "mapa.shared::cluster.u32 ra, %0, %1; st.shared::cluster.b64 [ra], d; }"
                         :: "r"(r0 + 8u), "r"(peer), "f"(lo4.z), "f"(lo4.w) : "memory");
            asm volatile("{ .reg .b32 ra; .reg .b64 d; mov.b64 d, {%2,%3}; "
                         "mapa.shared::cluster.u32 ra, %0, %1; st.shared::cluster.b64 [ra], d; }"
                         :: "r"(r1), "r"(peer), "f"(hi4.x), "f"(hi4.y) : "memory");
            asm volatile("{ .reg .b32 ra; .reg .b64 d; mov.b64 d, {%2,%3}; "
                         "mapa.shared::cluster.u32 ra, %0, %1; st.shared::cluster.b64 [ra], d; }"
                         :: "r"(r1 + 8u), "r"(peer), "f"(hi4.z), "f"(hi4.w) : "memory");
        }
        asm volatile("barrier.cluster.arrive.aligned;" ::: "memory");
        asm volatile("barrier.cluster.wait.aligned;" ::: "memory");
        p ^= 1;
    }

    // write final h: each CTA writes its j-half for the cluster's 8 batches
    const float* Hf = H + p * HBUF;
    int cb0 = cid * 8;
    for (int idx = tid; idx < 8 * JH; idx += STHREADS) {
        int b = idx / JH, jj = idx % JH;
        int j = rank * JH + jj;
        if (j < HDIM) out[(long long)(cb0 + b) * HDIM + j] = Hf[j * HSTRIDE + b];
    }
}

extern "C" void kernel_launch(void* const* d_in, const int* in_sizes, int n_in,
                              void* d_out, int out_size) {
    const float* IN  = (const float*)d_in[0];
    const float* Wih = (const float*)d_in[1];
    const float* Whh = (const float*)d_in[2];
    const float* bih = (const float*)d_in[3];
    const float* bhh = (const float*)d_in[4];
    float* out = (float*)d_out;

    prep_kernel<<<(IDIM * NP + 255) / 256, 256>>>(Wih, Whh, bih, bhh);

    dim3 g(NP / BN, MTOT / BM);   // (2, 2048)
    gemm_xproj<<<g, 256>>>(IN);

    size_t smem = (size_t)(WSZ + 2 * HBUF + PARTSZ) * sizeof(float);  // 216,448 B
    cudaFuncSetAttribute(scan_kernel, cudaFuncAttributeMaxDynamicSharedMemorySize, (int)smem);
    scan_kernel<<<128, STHREADS, smem>>>(out);
}

// round 7
// speedup vs baseline: 1.3208x; 1.2316x over previous
#include <cuda_runtime.h>
#include <cstdint>

#define SEQ   512
#define BATCH 512
#define IDIM  300
#define HDIM  300
#define NP    320            // padded hidden for XP layout
#define JH    152            // per-CTA j-half in scan (2*152 = 304 >= 300)
#define MTOT  (SEQ*BATCH)

#define BM 128
#define BN 160
#define BK 20

// scan config: 304 threads = 76 j-pairs x 4 k-quarters; 8 batch per thread
#define STHREADS 304
#define KQ       4
#define KCH      (IDIM/KQ)        // 75
#define HB       (304*8)          // one h buffer: [304 j][8 b] floats
#define WSZ      (IDIM*JH)        // 45600 floats
#define PARTU64  (8*STHREADS)     // partials: [8 u64-slots][304 tid]

// -------- scratch (static device globals; no allocations) --------
__device__ float g_XP[(long long)MTOT * NP];     // ~335 MB
__device__ float g_WihT[IDIM * NP];              // W_ih transposed+padded: [i][j]
__device__ float g_WT[2 * IDIM * JH];            // per-half W_hh transposed: [r][k][jj]
__device__ float g_bias[NP];                     // b_ih + b_hh (padded with 0)

// -------- f32x2 helpers (Blackwell packed fp32, PTX-only) --------
__device__ __forceinline__ unsigned long long pack2(float lo, float hi) {
    unsigned long long r;
    asm("mov.b64 %0, {%1, %2};" : "=l"(r) : "f"(lo), "f"(hi));
    return r;
}
__device__ __forceinline__ unsigned long long bcast2(float v) {
    unsigned long long r;
    asm("mov.b64 %0, {%1, %1};" : "=l"(r) : "f"(v));
    return r;
}
__device__ __forceinline__ void ffma2(unsigned long long& d, unsigned long long a, unsigned long long b) {
    asm("fma.rn.f32x2 %0, %1, %2, %3;" : "=l"(d) : "l"(a), "l"(b), "l"(d));
}
__device__ __forceinline__ void fadd2(unsigned long long& d, unsigned long long a) {
    asm("add.rn.f32x2 %0, %1, %2;" : "=l"(d) : "l"(d), "l"(a));
}
__device__ __forceinline__ void unpack2(unsigned long long v, float& lo, float& hi) {
    asm("mov.b64 {%0, %1}, %2;" : "=f"(lo), "=f"(hi) : "l"(v));
}
__device__ __forceinline__ uint32_t smem_u32(const void* p) {
    uint32_t a;
    asm("{ .reg .u64 t; cvta.to.shared.u64 t, %1; cvt.u32.u64 %0, t; }" : "=r"(a) : "l"(p));
    return a;
}

// -------- prep: transposes / padding / bias fold --------
__global__ void prep_kernel(const float* __restrict__ Wih, const float* __restrict__ Whh,
                            const float* __restrict__ bih, const float* __restrict__ bhh) {
    int i = blockIdx.x * blockDim.x + threadIdx.x;
    if (i < IDIM * NP) {
        int r = i / NP, j = i % NP;
        g_WihT[i] = (j < HDIM) ? Wih[j * IDIM + r] : 0.f;
    }
    if (i < 2 * IDIM * JH) {
        int rr  = i / (IDIM * JH);
        int rem = i % (IDIM * JH);
        int k = rem / JH, jj = rem % JH;
        int j = rr * JH + jj;
        g_WT[i] = (j < HDIM) ? Whh[j * HDIM + k] : 0.f;
    }
    if (i < NP) g_bias[i] = (i < HDIM) ? (bih[i] + bhh[i]) : 0.f;
}

// -------- x_proj GEMM: XP[m][j] = IN[m][:] . W_ih[j][:] + bias[j] --------
__global__ __launch_bounds__(256, 2) void gemm_xproj(const float* __restrict__ IN) {
    __shared__ float As[BM][BK + 1];  // [m][k], padded
    __shared__ float Bs[BK][BN];      // [k][n], n contiguous
    int tid = threadIdx.x;
    int m0 = blockIdx.y * BM;
    int n0 = blockIdx.x * BN;
    int mth = tid >> 4, nth = tid & 15;
    int tm0 = mth * 8, tn0 = nth * 10;

    unsigned long long acc[8][5];
    #pragma unroll
    for (int i = 0; i < 8; i++)
        #pragma unroll
        for (int u = 0; u < 5; u++) acc[i][u] = 0ull;

    for (int kk = 0; kk < IDIM; kk += BK) {
        #pragma unroll
        for (int l = 0; l < (BM * BK) / 256; l++) {
            int idx = tid + l * 256;
            int k = idx % BK, m = idx / BK;
            As[m][k] = IN[(long long)(m0 + m) * IDIM + kk + k];
        }
        for (int idx = tid * 4; idx < BK * BN; idx += 256 * 4) {
            int k = idx / BN, n = idx % BN;
            *(float4*)&Bs[k][n] = *(const float4*)&g_WihT[(long long)(kk + k) * NP + n0 + n];
        }
        __syncthreads();
        #pragma unroll 4
        for (int k = 0; k < BK; k++) {
            float a[8];
            #pragma unroll
            for (int i = 0; i < 8; i++) a[i] = As[tm0 + i][k];
            unsigned long long bv[5];
            const unsigned long long* Bk = (const unsigned long long*)&Bs[k][tn0];
            #pragma unroll
            for (int u = 0; u < 5; u++) bv[u] = Bk[u];
            #pragma unroll
            for (int i = 0; i < 8; i++) {
                unsigned long long aa = bcast2(a[i]);
                #pragma unroll
                for (int u = 0; u < 5; u++) ffma2(acc[i][u], aa, bv[u]);
            }
        }
        __syncthreads();
    }
    float bias[10];
    #pragma unroll
    for (int u = 0; u < 10; u++) bias[u] = g_bias[n0 + tn0 + u];
    #pragma unroll
    for (int i = 0; i < 8; i++) {
        long long row = (long long)(m0 + tm0 + i) * NP + n0 + tn0;
        #pragma unroll
        for (int u = 0; u < 5; u++) {
            float lo, hi; unpack2(acc[i][u], lo, hi);
            float2 v = make_float2(lo + bias[2 * u], hi + bias[2 * u + 1]);
            *(float2*)&g_XP[row + 2 * u] = v;
        }
    }
}

// -------- recurrent scan: 64 clusters x 2 CTAs, 8 batch per cluster --------
// 304 threads/CTA: thread = (j-pair jp, k-quarter kq); each covers 2j x 8b x 75k.
// Inner loop per k: LDS.64 (w pair, unique) + 2x LDS.128 (8 h, warp-broadcast)
// + 2 bcast + 8 FFMA2 -> W read ONCE per step (crossbar no longer binding).
// All threads store partials ([slot][tid], conflict-free), sync, then each
// thread reduces 4 outputs (j = tid>>1, b-quad = tid&1), adds prefetched xp,
// tanh, writes h to local + peer smem. Cluster barrier split (arrive ... wait)
// around the next step's XP global loads to hide both latencies.
__global__ __cluster_dims__(2, 1, 1) __launch_bounds__(STHREADS, 1)
void scan_kernel(float* __restrict__ out) {
    extern __shared__ float sm[];
    float* WT = sm;                                  // [300][152]
    float* H  = sm + WSZ;                            // [2][304*8]
    unsigned long long* PART = (unsigned long long*)(H + 2 * HB);  // [8][304]
    int tid = threadIdx.x;
    unsigned rank;
    asm("mov.u32 %0, %%cluster_ctarank;" : "=r"(rank));
    int cid = blockIdx.x >> 1;

    const float* WTg = g_WT + rank * WSZ;
    for (int i = tid; i < WSZ; i += STHREADS) WT[i] = WTg[i];
    for (int i = tid; i < 2 * HB; i += STHREADS) H[i] = 0.f;

    // compute-role indices
    int kq = tid / 76, jp = tid % 76;
    int j0 = jp * 2;
    const float* Wp0 = WT + kq * KCH * JH + j0;

    // reduce-role indices: output row jo (local), b-quad half
    int jo = tid >> 1, half = tid & 1;
    int jglob_o = rank * JH + jo;
    int hoff = jglob_o * 8 + half * 4;               // within an H buffer
    uint32_t hbase32 = smem_u32(H);
    unsigned peer = rank ^ 1u;
    const float* xpbase = g_XP + (long long)(cid * 8 + half * 4) * NP + jglob_o;

    asm volatile("barrier.cluster.arrive.aligned;" ::: "memory");
    int p = 0;

    for (int t = 0; t < SEQ; t++) {
        // prefetch xp for this step's 4 outputs (between arrive and wait)
        const float* xr = xpbase + (long long)t * BATCH * NP;
        float x0 = xr[0];
        float x1 = xr[NP];
        float x2 = xr[2 * NP];
        float x3 = xr[3 * NP];

        asm volatile("barrier.cluster.wait.aligned;" ::: "memory");

        // main MAC loop over this thread's k-quarter
        unsigned long long A00 = 0, A01 = 0, A02 = 0, A03 = 0;
        unsigned long long A10 = 0, A11 = 0, A12 = 0, A13 = 0;
        const float* Wp = Wp0;
        const float* hp = H + p * HB + kq * KCH * 8;
        #pragma unroll 5
        for (int kk = 0; kk < KCH; kk++) {
            float2 w = *(const float2*)(Wp + kk * JH);
            ulonglong2 hA = *(const ulonglong2*)(hp + kk * 8);
            ulonglong2 hB = *(const ulonglong2*)(hp + kk * 8 + 4);
            unsigned long long w0 = bcast2(w.x);
            unsigned long long w1 = bcast2(w.y);
            ffma2(A00, w0, hA.x); ffma2(A01, w0, hA.y);
            ffma2(A02, w0, hB.x); ffma2(A03, w0, hB.y);
            ffma2(A10, w1, hA.x); ffma2(A11, w1, hA.y);
            ffma2(A12, w1, hB.x); ffma2(A13, w1, hB.y);
        }
        // store partials: slot s = r*4 + c, layout [s][tid] (conflict-free)
        PART[0 * STHREADS + tid] = A00;
        PART[1 * STHREADS + tid] = A01;
        PART[2 * STHREADS + tid] = A02;
        PART[3 * STHREADS + tid] = A03;
        PART[4 * STHREADS + tid] = A10;
        PART[5 * STHREADS + tid] = A11;
        PART[6 * STHREADS + tid] = A12;
        PART[7 * STHREADS + tid] = A13;
        __syncthreads();

        // reduce 4 k-quarters for outputs (jo, b half*4 .. half*4+3)
        int jps = jo >> 1;                 // source j-pair
        int r = jo & 1;                    // row within pair
        int s0 = r * 4 + half * 2;         // slot of b-pair (b0,b1) of this half
        unsigned long long acc0 = PART[s0 * STHREADS + jps];
        unsigned long long acc1 = PART[(s0 + 1) * STHREADS + jps];
        #pragma unroll
        for (int q = 1; q < KQ; q++) {
            int src = q * 76 + jps;
            fadd2(acc0, PART[s0 * STHREADS + src]);
            fadd2(acc1, PART[(s0 + 1) * STHREADS + src]);
        }
        float v0, v1, v2, v3;
        unpack2(acc0, v0, v1);
        unpack2(acc1, v2, v3);
        float4 hv = make_float4(tanhf(x0 + v0), tanhf(x1 + v1),
                                tanhf(x2 + v2), tanhf(x3 + v3));
        int off = (1 - p) * HB + hoff;
        *(float4*)(H + off) = hv;
        uint32_t ra = hbase32 + off * 4;
        asm volatile("{ .reg .b32 pa; .reg .b64 d; mov.b64 d, {%2,%3}; "
                     "mapa.shared::cluster.u32 pa, %0, %1; st.shared::cluster.b64 [pa], d; }"
                     :: "r"(ra), "r"(peer), "f"(hv.x), "f"(hv.y) : "memory");
        asm volatile("{ .reg .b32 pa; .reg .b64 d; mov.b64 d, {%2,%3}; "
                     "mapa.shared::cluster.u32 pa, %0, %1; st.shared::cluster.b64 [pa], d; }"
                     :: "r"(ra + 8u), "r"(peer), "f"(hv.z), "f"(hv.w) : "memory");

        asm volatile("barrier.cluster.arrive.aligned;" ::: "memory");
        p ^= 1;
    }
    asm volatile("barrier.cluster.wait.aligned;" ::: "memory");

    // write final h: each CTA writes its j-half for the cluster's 8 batches
    const float* Hf = H + p * HB;
    int cb0 = cid * 8;
    for (int idx = tid; idx < 8 * JH; idx += STHREADS) {
        int b = idx / JH, jj = idx % JH;
        int j = rank * JH + jj;
        if (j < HDIM) out[(long long)(cb0 + b) * HDIM + j] = Hf[j * 8 + b];
    }
    asm volatile("barrier.cluster.arrive.aligned;" ::: "memory");
    asm volatile("barrier.cluster.wait.aligned;" ::: "memory");
}

extern "C" void kernel_launch(void* const* d_in, const int* in_sizes, int n_in,
                              void* d_out, int out_size) {
    const float* IN  = (const float*)d_in[0];
    const float* Wih = (const float*)d_in[1];
    const float* Whh = (const float*)d_in[2];
    const float* bih = (const float*)d_in[3];
    const float* bhh = (const float*)d_in[4];
    float* out = (float*)d_out;

    prep_kernel<<<(IDIM * NP + 255) / 256, 256>>>(Wih, Whh, bih, bhh);

    dim3 g(NP / BN, MTOT / BM);   // (2, 2048)
    gemm_xproj<<<g, 256>>>(IN);

    // smem: WT 182400B + H 19456B + PART 19456B = 221,312 B
    size_t smem = (size_t)(WSZ + 2 * HB) * sizeof(float) + PARTU64 * sizeof(unsigned long long);
    cudaFuncSetAttribute(scan_kernel, cudaFuncAttributeMaxDynamicSharedMemorySize, (int)smem);
    scan_kernel<<<128, STHREADS, smem>>>(out);
}

// round 8
// speedup vs baseline: 1.3314x; 1.0080x over previous
#include <cuda_runtime.h>
#include <cstdint>

#define SEQ   512
#define BATCH 512
#define IDIM  300
#define HDIM  300
#define NP    320            // padded hidden for XP layout
#define JH    152            // per-CTA j-half in scan (2*152 = 304 >= 300)
#define MTOT  (SEQ*BATCH)

// GEMM tiling: 64x160 tile, 256 threads, 4m x 10n per thread (40 acc regs -> occ 3)
#define BM 64
#define BN 160
#define BK 20
#define GTH 256

// scan config: 304 threads = 76 j-pairs x 4 k-quarters; 8 batch per thread
#define STHREADS 304
#define KQ       4
#define KCH      (IDIM/KQ)        // 75
#define HB       (304*8)          // one h buffer: [304 j][8 b] floats
#define WSZ      (IDIM*JH)        // 45600 floats
#define PARTU64  (8*STHREADS)     // partials: [8 u64-slots][304 tid]

// -------- scratch (static device globals; no allocations) --------
__device__ float g_XP[(long long)MTOT * NP];     // ~335 MB
__device__ float g_WihT[IDIM * NP];              // W_ih transposed+padded: [i][j]
__device__ float g_WT[2 * IDIM * JH];            // per-half W_hh transposed: [r][k][jj]
__device__ float g_bias[NP];                     // b_ih + b_hh (padded with 0)

// -------- f32x2 helpers (Blackwell packed fp32, PTX-only) --------
__device__ __forceinline__ unsigned long long pack2(float lo, float hi) {
    unsigned long long r;
    asm("mov.b64 %0, {%1, %2};" : "=l"(r) : "f"(lo), "f"(hi));
    return r;
}
__device__ __forceinline__ unsigned long long bcast2(float v) {
    unsigned long long r;
    asm("mov.b64 %0, {%1, %1};" : "=l"(r) : "f"(v));
    return r;
}
__device__ __forceinline__ void ffma2(unsigned long long& d, unsigned long long a, unsigned long long b) {
    asm("fma.rn.f32x2 %0, %1, %2, %3;" : "=l"(d) : "l"(a), "l"(b), "l"(d));
}
__device__ __forceinline__ void fadd2(unsigned long long& d, unsigned long long a) {
    asm("add.rn.f32x2 %0, %1, %2;" : "=l"(d) : "l"(d), "l"(a));
}
__device__ __forceinline__ void unpack2(unsigned long long v, float& lo, float& hi) {
    asm("mov.b64 {%0, %1}, %2;" : "=f"(lo), "=f"(hi) : "l"(v));
}
__device__ __forceinline__ uint32_t smem_u32(const void* p) {
    uint32_t a;
    asm("{ .reg .u64 t; cvta.to.shared.u64 t, %1; cvt.u32.u64 %0, t; }" : "=r"(a) : "l"(p));
    return a;
}
// fast tanh: 1 - 2/(exp(2x)+1); saturates correctly (exp->inf => 1, exp->0 => -1)
__device__ __forceinline__ float fast_tanh(float x) {
    float e = __expf(2.0f * x);
    return 1.0f - __fdividef(2.0f, e + 1.0f);
}

// -------- prep: transposes / padding / bias fold --------
__global__ void prep_kernel(const float* __restrict__ Wih, const float* __restrict__ Whh,
                            const float* __restrict__ bih, const float* __restrict__ bhh) {
    int i = blockIdx.x * blockDim.x + threadIdx.x;
    if (i < IDIM * NP) {
        int r = i / NP, j = i % NP;
        g_WihT[i] = (j < HDIM) ? Wih[j * IDIM + r] : 0.f;
    }
    if (i < 2 * IDIM * JH) {
        int rr  = i / (IDIM * JH);
        int rem = i % (IDIM * JH);
        int k = rem / JH, jj = rem % JH;
        int j = rr * JH + jj;
        g_WT[i] = (j < HDIM) ? Whh[j * HDIM + k] : 0.f;
    }
    if (i < NP) g_bias[i] = (i < HDIM) ? (bih[i] + bhh[i]) : 0.f;
}

// -------- x_proj GEMM: XP[m][j] = IN[m][:] . W_ih[j][:] + bias[j] --------
// 64x160 tile, 256 threads, thread tile 4m x 10n (acc = 20 f32x2 = 40 regs),
// occupancy 3 (18 warps/SM) so global-load latency and syncs are hidden.
__global__ __launch_bounds__(GTH, 3) void gemm_xproj(const float* __restrict__ IN) {
    __shared__ float As[BK][BM + 4];  // [k][m], padded
    __shared__ float Bs[BK][BN];      // [k][n], n contiguous
    int tid = threadIdx.x;
    int m0 = blockIdx.y * BM;
    int n0 = blockIdx.x * BN;
    int mth = tid >> 4, nth = tid & 15;   // 16 x 16
    int tm0 = mth * 4, tn0 = nth * 10;

    unsigned long long acc[4][5];
    #pragma unroll
    for (int i = 0; i < 4; i++)
        #pragma unroll
        for (int u = 0; u < 5; u++) acc[i][u] = 0ull;

    for (int kk = 0; kk < IDIM; kk += BK) {
        // As: 64x20 = 1280 floats, 5 per thread, transposed store [k][m]
        #pragma unroll
        for (int l = 0; l < (BM * BK) / GTH; l++) {
            int idx = tid + l * GTH;
            int m = idx / BK, k = idx % BK;
            As[k][m] = IN[(long long)(m0 + m) * IDIM + kk + k];
        }
        // Bs: 20x160 = 3200 floats, float2 loads (coalesced from g_WihT)
        #pragma unroll
        for (int idx = tid; idx < (BK * BN) / 2; idx += GTH) {
            int k = idx / (BN / 2), n2 = idx % (BN / 2);
            *(float2*)&Bs[k][n2 * 2] =
                *(const float2*)&g_WihT[(long long)(kk + k) * NP + n0 + n2 * 2];
        }
        __syncthreads();
        #pragma unroll
        for (int k = 0; k < BK; k++) {
            float4 av = *(const float4*)&As[k][tm0];
            const unsigned long long* Bk = (const unsigned long long*)&Bs[k][tn0];
            unsigned long long b0 = Bk[0], b1 = Bk[1], b2 = Bk[2], b3 = Bk[3], b4 = Bk[4];
            unsigned long long a0 = bcast2(av.x), a1 = bcast2(av.y);
            unsigned long long a2 = bcast2(av.z), a3 = bcast2(av.w);
            ffma2(acc[0][0], a0, b0); ffma2(acc[0][1], a0, b1); ffma2(acc[0][2], a0, b2);
            ffma2(acc[0][3], a0, b3); ffma2(acc[0][4], a0, b4);
            ffma2(acc[1][0], a1, b0); ffma2(acc[1][1], a1, b1); ffma2(acc[1][2], a1, b2);
            ffma2(acc[1][3], a1, b3); ffma2(acc[1][4], a1, b4);
            ffma2(acc[2][0], a2, b0); ffma2(acc[2][1], a2, b1); ffma2(acc[2][2], a2, b2);
            ffma2(acc[2][3], a2, b3); ffma2(acc[2][4], a2, b4);
            ffma2(acc[3][0], a3, b0); ffma2(acc[3][1], a3, b1); ffma2(acc[3][2], a3, b2);
            ffma2(acc[3][3], a3, b3); ffma2(acc[3][4], a3, b4);
        }
        __syncthreads();
    }
    float bias[10];
    #pragma unroll
    for (int u = 0; u < 10; u++) bias[u] = g_bias[n0 + tn0 + u];
    #pragma unroll
    for (int i = 0; i < 4; i++) {
        long long row = (long long)(m0 + tm0 + i) * NP + n0 + tn0;
        #pragma unroll
        for (int u = 0; u < 5; u++) {
            float lo, hi; unpack2(acc[i][u], lo, hi);
            float2 v = make_float2(lo + bias[2 * u], hi + bias[2 * u + 1]);
            *(float2*)&g_XP[row + 2 * u] = v;
        }
    }
}

// -------- recurrent scan: 64 clusters x 2 CTAs, 8 batch per cluster --------
// 304 threads/CTA: thread = (j-pair jp, k-quarter kq); each covers 2j x 8b x 75k.
// Inner loop per k: LDS.64 (w pair, unique) + 2x LDS.128 (8 h, warp-broadcast)
// + 2 bcast + 8 FFMA2 -> W read ONCE per step. Partials reduced via smem; each
// thread then finishes 4 outputs with fast_tanh and writes h to local + peer
// CTA smem. Cluster barrier split (arrive ... wait) around next step's XP loads.
__global__ __cluster_dims__(2, 1, 1) __launch_bounds__(STHREADS, 1)
void scan_kernel(float* __restrict__ out) {
    extern __shared__ float sm[];
    float* WT = sm;                                  // [300][152]
    float* H  = sm + WSZ;                            // [2][304*8]
    unsigned long long* PART = (unsigned long long*)(H + 2 * HB);  // [8][304]
    int tid = threadIdx.x;
    unsigned rank;
    asm("mov.u32 %0, %%cluster_ctarank;" : "=r"(rank));
    int cid = blockIdx.x >> 1;

    const float* WTg = g_WT + rank * WSZ;
    for (int i = tid; i < WSZ; i += STHREADS) WT[i] = WTg[i];
    for (int i = tid; i < 2 * HB; i += STHREADS) H[i] = 0.f;

    // compute-role indices
    int kq = tid / 76, jp = tid % 76;
    int j0 = jp * 2;
    const float* Wp0 = WT + kq * KCH * JH + j0;

    // reduce-role indices: output row jo (local), b-quad half
    int jo = tid >> 1, half = tid & 1;
    int jglob_o = rank * JH + jo;
    int hoff = jglob_o * 8 + half * 4;               // within an H buffer
    uint32_t hbase32 = smem_u32(H);
    unsigned peer = rank ^ 1u;
    const float* xpbase = g_XP + (long long)(cid * 8 + half * 4) * NP + jglob_o;

    asm volatile("barrier.cluster.arrive.aligned;" ::: "memory");
    int p = 0;

    for (int t = 0; t < SEQ; t++) {
        // prefetch xp for this step's 4 outputs (between arrive and wait)
        const float* xr = xpbase + (long long)t * BATCH * NP;
        float x0 = xr[0];
        float x1 = xr[NP];
        float x2 = xr[2 * NP];
        float x3 = xr[3 * NP];

        asm volatile("barrier.cluster.wait.aligned;" ::: "memory");

        // main MAC loop over this thread's k-quarter
        unsigned long long A00 = 0, A01 = 0, A02 = 0, A03 = 0;
        unsigned long long A10 = 0, A11 = 0, A12 = 0, A13 = 0;
        const float* Wp = Wp0;
        const float* hp = H + p * HB + kq * KCH * 8;
        #pragma unroll 15
        for (int kk = 0; kk < KCH; kk++) {
            float2 w = *(const float2*)(Wp + kk * JH);
            ulonglong2 hA = *(const ulonglong2*)(hp + kk * 8);
            ulonglong2 hB = *(const ulonglong2*)(hp + kk * 8 + 4);
            unsigned long long w0 = bcast2(w.x);
            unsigned long long w1 = bcast2(w.y);
            ffma2(A00, w0, hA.x); ffma2(A01, w0, hA.y);
            ffma2(A02, w0, hB.x); ffma2(A03, w0, hB.y);
            ffma2(A10, w1, hA.x); ffma2(A11, w1, hA.y);
            ffma2(A12, w1, hB.x); ffma2(A13, w1, hB.y);
        }
        // store partials: slot s, layout [s][tid] (conflict-free)
        PART[0 * STHREADS + tid] = A00;
        PART[1 * STHREADS + tid] = A01;
        PART[2 * STHREADS + tid] = A02;
        PART[3 * STHREADS + tid] = A03;
        PART[4 * STHREADS + tid] = A10;
        PART[5 * STHREADS + tid] = A11;
        PART[6 * STHREADS + tid] = A12;
        PART[7 * STHREADS + tid] = A13;
        __syncthreads();

        // reduce 4 k-quarters for outputs (jo, b half*4 .. half*4+3)
        int jps = jo >> 1;                 // source j-pair
        int r = jo & 1;                    // row within pair
        int s0 = r * 4 + half * 2;         // slot of b-pair (b0,b1) of this half
        unsigned long long acc0 = PART[s0 * STHREADS + jps];
        unsigned long long acc1 = PART[(s0 + 1) * STHREADS + jps];
        #pragma unroll
        for (int q = 1; q < KQ; q++) {
            int src = q * 76 + jps;
            fadd2(acc0, PART[s0 * STHREADS + src]);
            fadd2(acc1, PART[(s0 + 1) * STHREADS + src]);
        }
        float v0, v1, v2, v3;
        unpack2(acc0, v0, v1);
        unpack2(acc1, v2, v3);
        float4 hv = make_float4(fast_tanh(x0 + v0), fast_tanh(x1 + v1),
                                fast_tanh(x2 + v2), fast_tanh(x3 + v3));
        int off = (1 - p) * HB + hoff;
        *(float4*)(H + off) = hv;
        uint32_t ra = hbase32 + off * 4;
        asm volatile("{ .reg .b32 pa; .reg .b64 d; mov.b64 d, {%2,%3}; "
                     "mapa.shared::cluster.u32 pa, %0, %1; st.shared::cluster.b64 [pa], d; }"
                     :: "r"(ra), "r"(peer), "f"(hv.x), "f"(hv.y) : "memory");
        asm volatile("{ .reg .b32 pa; .reg .b64 d; mov.b64 d, {%2,%3}; "
                     "mapa.shared::cluster.u32 pa, %0, %1; st.shared::cluster.b64 [pa], d; }"
                     :: "r"(ra + 8u), "r"(peer), "f"(hv.z), "f"(hv.w) : "memory");

        asm volatile("barrier.cluster.arrive.aligned;" ::: "memory");
        p ^= 1;
    }
    asm volatile("barrier.cluster.wait.aligned;" ::: "memory");

    // write final h: each CTA writes its j-half for the cluster's 8 batches
    const float* Hf = H + p * HB;
    int cb0 = cid * 8;
    for (int idx = tid; idx < 8 * JH; idx += STHREADS) {
        int b = idx / JH, jj = idx % JH;
        int j = rank * JH + jj;
        if (j < HDIM) out[(long long)(cb0 + b) * HDIM + j] = Hf[j * 8 + b];
    }
    asm volatile("barrier.cluster.arrive.aligned;" ::: "memory");
    asm volatile("barrier.cluster.wait.aligned;" ::: "memory");
}

extern "C" void kernel_launch(void* const* d_in, const int* in_sizes, int n_in,
                              void* d_out, int out_size) {
    const float* IN  = (const float*)d_in[0];
    const float* Wih = (const float*)d_in[1];
    const float* Whh = (const float*)d_in[2];
    const float* bih = (const float*)d_in[3];
    const float* bhh = (const float*)d_in[4];
    float* out = (float*)d_out;

    prep_kernel<<<(IDIM * NP + 255) / 256, 256>>>(Wih, Whh, bih, bhh);

    dim3 g(NP / BN, MTOT / BM);   // (2, 4096)
    gemm_xproj<<<g, GTH>>>(IN);

    // smem: WT 182400B + H 19456B + PART 19456B = 221,312 B
    size_t smem = (size_t)(WSZ + 2 * HB) * sizeof(float) + PARTU64 * sizeof(unsigned long long);
    cudaFuncSetAttribute(scan_kernel, cudaFuncAttributeMaxDynamicSharedMemorySize, (int)smem);
    scan_kernel<<<128, STHREADS, smem>>>(out);
}